// round 16
// baseline (speedup 1.0000x reference)
#include <cuda_runtime.h>

#define N_NODES 100000
#define N_EDGES 1000000
#define N_GRAPHS 128

typedef unsigned long long u64t;

// ---------------- packed f32x2 helpers --------------------------------------
__device__ __forceinline__ u64t ffma2(u64t a, u64t b, u64t c) {
    u64t d;
    asm("fma.rn.f32x2 %0, %1, %2, %3;" : "=l"(d) : "l"(a), "l"(b), "l"(c));
    return d;
}
__device__ __forceinline__ u64t pack2(float lo, float hi) {
    u64t r;
    asm("mov.b64 %0, {%1, %2};" : "=l"(r) : "f"(lo), "f"(hi));
    return r;
}
__device__ __forceinline__ float2 unpack2(u64t v) {
    float2 r;
    asm("mov.b64 {%0, %1}, %2;" : "=f"(r.x), "=f"(r.y) : "l"(v));
    return r;
}

// ---------------- scratch ----------------------------------------------------
__device__ __align__(16) float g_aggr[N_NODES * 64];
__device__ __align__(16) float g_h1[N_NODES * 64];
__device__ __align__(16) float g_pool[N_GRAPHS * 64];

// ---------------- aggr = (1+eps1) * x ---------------------------------------
__global__ __launch_bounds__(256) void k_init(const float4* __restrict__ x,
                                              const float* __restrict__ eps,
                                              float4* __restrict__ aggr) {
    int i = blockIdx.x * blockDim.x + threadIdx.x;
    float s = 1.0f + *eps;
    float4 v = x[i];
    v.x *= s; v.y *= s; v.z *= s; v.w *= s;
    aggr[i] = v;
}

// ---------------- edge kernel v4: early acc-fold, 4 blocks/SM -----------------
// R10 mainloop/epilogue; restructured prologue so gathered x rows fold into
// the accumulators BEFORE ea staging (shrinks the live-register window:
// peak ~100 regs -> 4 blocks x 160 thr = 20 warps/SM).
#define EPB 160
__global__ void __launch_bounds__(160, 4)
k_edge(const float4* __restrict__ x4,
       const float4* __restrict__ ea4,
       const int* __restrict__ src,
       const int* __restrict__ dst,
       const float4* __restrict__ We4,
       const float4* __restrict__ be4,
       float4* __restrict__ aggr4) {
    __shared__ float4 sEA4[EPB * 9];
    __shared__ u64t   sW[32][32];
    __shared__ int    sDst[EPB];

    const int tid   = threadIdx.x;
    const int e0    = blockIdx.x * EPB;
    const int cg    = tid & 7;
    const int eg    = tid >> 3;
    const int ebase = eg * 8;
    const int fA    = cg;
    const int fB    = 8 + cg;
    const int sw    = eg & 3;

    // 1) issue gathers
    int mySrc[8];
#pragma unroll
    for (int i = 0; i < 8; i++) mySrc[i] = __ldg(&src[e0 + ebase + i]);
    float4 xa[8], xb[8];
#pragma unroll
    for (int i = 0; i < 8; i++) {
        xa[i] = __ldg(&x4[(size_t)mySrc[i] * 16 + fA]);
        xb[i] = __ldg(&x4[(size_t)mySrc[i] * 16 + fB]);
    }

    // 2) stage We (hides part of the gather latency)
    for (int i = tid; i < 512; i += EPB) {
        int k = i >> 4, c4 = i & 15;
        float4 v = We4[i];
        sW[k][2 * c4]     = pack2(v.x, v.y);
        sW[k][2 * c4 + 1] = pack2(v.z, v.w);
    }

    // 3) fold gathers + bias into accumulators NOW (kills xa/xb liveness
    //    before the ea staging loop)
    float4 b0 = __ldg(&be4[fA]);
    float4 b1 = __ldg(&be4[fB]);
    u64t acc[8][4];
#pragma unroll
    for (int i = 0; i < 8; i++) {
        acc[i][0] = pack2(b0.x + xa[i].x, b0.y + xa[i].y);
        acc[i][1] = pack2(b0.z + xa[i].z, b0.w + xa[i].w);
        acc[i][2] = pack2(b1.x + xb[i].x, b1.y + xb[i].y);
        acc[i][3] = pack2(b1.z + xb[i].z, b1.w + xb[i].w);
    }

    // 4) stage ea (swizzled) + dst
#pragma unroll
    for (int i = tid; i < EPB * 8; i += EPB) {
        int e = i >> 3, q = i & 7;
        sEA4[e * 9 + (q ^ ((e >> 3) & 3))] = ea4[(size_t)(e0 + e) * 8 + q];
    }
    if (tid < EPB) sDst[tid] = dst[e0 + tid];
    __syncthreads();

    // 5) mainloop (identical to R10)
#pragma unroll
    for (int k4 = 0; k4 < 8; k4++) {
#pragma unroll
        for (int h = 0; h < 2; h++) {
            float4 eav[4];
#pragma unroll
            for (int i = 0; i < 4; i++)
                eav[i] = sEA4[(ebase + h * 4 + i) * 9 + (k4 ^ sw)];
#pragma unroll
            for (int kk = 0; kk < 4; kk++) {
                int k = k4 * 4 + kk;
                ulonglong2 wA = *(const ulonglong2*)&sW[k][2 * cg];
                ulonglong2 wB = *(const ulonglong2*)&sW[k][16 + 2 * cg];
#pragma unroll
                for (int i = 0; i < 4; i++) {
                    int e = h * 4 + i;
                    float a = (kk == 0) ? eav[i].x : (kk == 1) ? eav[i].y
                            : (kk == 2) ? eav[i].z : eav[i].w;
                    u64t aa = pack2(a, a);
                    acc[e][0] = ffma2(aa, wA.x, acc[e][0]);
                    acc[e][1] = ffma2(aa, wA.y, acc[e][1]);
                    acc[e][2] = ffma2(aa, wB.x, acc[e][2]);
                    acc[e][3] = ffma2(aa, wB.y, acc[e][3]);
                }
            }
        }
    }

    // 6) epilogue: relu + scatter-add (identical to R10)
#pragma unroll
    for (int e = 0; e < 8; e++) {
        float2 v0 = unpack2(acc[e][0]);
        float2 v1 = unpack2(acc[e][1]);
        float2 v2 = unpack2(acc[e][2]);
        float2 v3 = unpack2(acc[e][3]);
        float4 m0, m1;
        m0.x = fmaxf(v0.x, 0.0f); m0.y = fmaxf(v0.y, 0.0f);
        m0.z = fmaxf(v1.x, 0.0f); m0.w = fmaxf(v1.y, 0.0f);
        m1.x = fmaxf(v2.x, 0.0f); m1.y = fmaxf(v2.y, 0.0f);
        m1.z = fmaxf(v3.x, 0.0f); m1.w = fmaxf(v3.y, 0.0f);
        int d = sDst[ebase + e];
        atomicAdd(&aggr4[(size_t)d * 16 + fA], m0);
        atomicAdd(&aggr4[(size_t)d * 16 + fB], m1);
    }
}

// ---------------- node MLP v2 (R7/R10 verbatim — best measured) --------------
#define MLP_NPB 256
#define PADF 260
#define MLP_SMEM (2 * 64 * 64 * 4 + 64 * PADF * 4)
template <bool POOL>
__global__ void __launch_bounds__(256, 2)
k_mlp(const float4* __restrict__ hin4,
      const float4* __restrict__ W1_4,
      const float4* __restrict__ b1_4,
      const float4* __restrict__ W2_4,
      const float4* __restrict__ b2_4,
      float4* __restrict__ hout4,
      const float* __restrict__ eps_next,
      float4* __restrict__ aggr_next,
      const int* __restrict__ batch,
      float4* __restrict__ pool4) {
    extern __shared__ char smem_raw[];
    float4* sW1f4 = (float4*)smem_raw;
    float4* sW2f4 = sW1f4 + 64 * 16;
    float*  sHT   = (float*)(sW2f4 + 64 * 16);

    const int tid = threadIdx.x;
    const int n0  = blockIdx.x * MLP_NPB;
    const int cg  = tid & 7;
    const int ng  = tid >> 3;

    for (int i = tid; i < 1024; i += 256) {
        sW1f4[i] = W1_4[i];
        sW2f4[i] = W2_4[i];
    }
    for (int i = tid; i < MLP_NPB * 16; i += 256) {
        int n = i & 255, k4 = i >> 8;
        float4 v = (n0 + n < N_NODES) ? hin4[(size_t)(n0 + n) * 16 + k4]
                                      : make_float4(0.f, 0.f, 0.f, 0.f);
        sHT[(4 * k4 + 0) * PADF + n] = v.x;
        sHT[(4 * k4 + 1) * PADF + n] = v.y;
        sHT[(4 * k4 + 2) * PADF + n] = v.z;
        sHT[(4 * k4 + 3) * PADF + n] = v.w;
    }
    __syncthreads();

    u64t acc[4][8];
    {
        float4 ba = __ldg(&b1_4[cg]);
        float4 bb = __ldg(&b1_4[8 + cg]);
        u64t bi[8] = { pack2(ba.x, ba.x), pack2(ba.y, ba.y),
                       pack2(ba.z, ba.z), pack2(ba.w, ba.w),
                       pack2(bb.x, bb.x), pack2(bb.y, bb.y),
                       pack2(bb.z, bb.z), pack2(bb.w, bb.w) };
#pragma unroll
        for (int np = 0; np < 4; np++)
#pragma unroll
            for (int c = 0; c < 8; c++) acc[np][c] = bi[c];
    }

#pragma unroll 8
    for (int k = 0; k < 64; k++) {
        ulonglong2 hA = *(const ulonglong2*)&sHT[k * PADF + 8 * ng];
        ulonglong2 hB = *(const ulonglong2*)&sHT[k * PADF + 8 * ng + 4];
        float4 wa = sW1f4[k * 16 + cg];
        float4 wb = sW1f4[k * 16 + 8 + cg];
        u64t w2[8] = { pack2(wa.x, wa.x), pack2(wa.y, wa.y),
                       pack2(wa.z, wa.z), pack2(wa.w, wa.w),
                       pack2(wb.x, wb.x), pack2(wb.y, wb.y),
                       pack2(wb.z, wb.z), pack2(wb.w, wb.w) };
        u64t hp[4] = { hA.x, hA.y, hB.x, hB.y };
#pragma unroll
        for (int np = 0; np < 4; np++)
#pragma unroll
            for (int c = 0; c < 8; c++)
                acc[np][c] = ffma2(hp[np], w2[c], acc[np][c]);
    }
    __syncthreads();
#pragma unroll
    for (int np = 0; np < 4; np++) {
#pragma unroll
        for (int c = 0; c < 8; c++) {
            float2 v = unpack2(acc[np][c]);
            int cglob = (c < 4) ? (4 * cg + c) : (32 + 4 * cg + (c - 4));
            float2 t = make_float2(fmaxf(v.x, 0.0f), fmaxf(v.y, 0.0f));
            *(float2*)&sHT[cglob * PADF + 8 * ng + 2 * np] = t;
        }
    }
    __syncthreads();

    {
        float4 ba = __ldg(&b2_4[cg]);
        float4 bb = __ldg(&b2_4[8 + cg]);
        u64t bi[8] = { pack2(ba.x, ba.x), pack2(ba.y, ba.y),
                       pack2(ba.z, ba.z), pack2(ba.w, ba.w),
                       pack2(bb.x, bb.x), pack2(bb.y, bb.y),
                       pack2(bb.z, bb.z), pack2(bb.w, bb.w) };
#pragma unroll
        for (int np = 0; np < 4; np++)
#pragma unroll
            for (int c = 0; c < 8; c++) acc[np][c] = bi[c];
    }
#pragma unroll 8
    for (int k = 0; k < 64; k++) {
        ulonglong2 hA = *(const ulonglong2*)&sHT[k * PADF + 8 * ng];
        ulonglong2 hB = *(const ulonglong2*)&sHT[k * PADF + 8 * ng + 4];
        float4 wa = sW2f4[k * 16 + cg];
        float4 wb = sW2f4[k * 16 + 8 + cg];
        u64t w2[8] = { pack2(wa.x, wa.x), pack2(wa.y, wa.y),
                       pack2(wa.z, wa.z), pack2(wa.w, wa.w),
                       pack2(wb.x, wb.x), pack2(wb.y, wb.y),
                       pack2(wb.z, wb.z), pack2(wb.w, wb.w) };
        u64t hp[4] = { hA.x, hA.y, hB.x, hB.y };
#pragma unroll
        for (int np = 0; np < 4; np++)
#pragma unroll
            for (int c = 0; c < 8; c++)
                acc[np][c] = ffma2(hp[np], w2[c], acc[np][c]);
    }

    float s = POOL ? 0.0f : (1.0f + __ldg(eps_next));
#pragma unroll
    for (int np = 0; np < 4; np++) {
        float2 p[8];
#pragma unroll
        for (int c = 0; c < 8; c++) p[c] = unpack2(acc[np][c]);
#pragma unroll
        for (int b = 0; b < 2; b++) {
            int node = n0 + 8 * ng + 2 * np + b;
            if (node >= N_NODES) continue;
            float4 oA, oB;
            oA.x = fmaxf(b ? p[0].y : p[0].x, 0.0f);
            oA.y = fmaxf(b ? p[1].y : p[1].x, 0.0f);
            oA.z = fmaxf(b ? p[2].y : p[2].x, 0.0f);
            oA.w = fmaxf(b ? p[3].y : p[3].x, 0.0f);
            oB.x = fmaxf(b ? p[4].y : p[4].x, 0.0f);
            oB.y = fmaxf(b ? p[5].y : p[5].x, 0.0f);
            oB.z = fmaxf(b ? p[6].y : p[6].x, 0.0f);
            oB.w = fmaxf(b ? p[7].y : p[7].x, 0.0f);
            if (POOL) {
                int g = __ldg(&batch[node]);
                atomicAdd(&pool4[(size_t)g * 16 + cg], oA);
                atomicAdd(&pool4[(size_t)g * 16 + 8 + cg], oB);
            } else {
                hout4[(size_t)node * 16 + cg]     = oA;
                hout4[(size_t)node * 16 + 8 + cg] = oB;
                float4 zA, zB;
                zA.x = s * oA.x; zA.y = s * oA.y; zA.z = s * oA.z; zA.w = s * oA.w;
                zB.x = s * oB.x; zB.y = s * oB.y; zB.z = s * oB.z; zB.w = s * oB.w;
                aggr_next[(size_t)node * 16 + cg]     = zA;
                aggr_next[(size_t)node * 16 + 8 + cg] = zB;
            }
        }
    }
}

// ---------------- head -------------------------------------------------------
__global__ __launch_bounds__(128) void k_head(const float* __restrict__ pool,
                                              const float* __restrict__ Wf1,
                                              const float* __restrict__ bf1,
                                              const float* __restrict__ Wf2,
                                              const float* __restrict__ bf2,
                                              float* __restrict__ out) {
    __shared__ float sW[64][128];
    const int tid = threadIdx.x;
    for (int i = tid; i < 64 * 128; i += 128) sW[i >> 7][i & 127] = Wf1[i];
    __syncthreads();

    float p[64];
#pragma unroll
    for (int k = 0; k < 64; k++) p[k] = pool[tid * 64 + k];

    float o = 0.0f;
    for (int j = 0; j < 128; j++) {
        float s = bf1[j];
#pragma unroll
        for (int k = 0; k < 64; k++) s = fmaf(p[k], sW[k][j], s);
        o = fmaf(fmaxf(s, 0.0f), Wf2[j], o);
    }
    out[tid] = o + bf2[0];
}

// ---------------- launch -----------------------------------------------------
extern "C" void kernel_launch(void* const* d_in, const int* in_sizes, int n_in,
                              void* d_out, int out_size) {
    const float* x    = (const float*)d_in[0];
    const float* ea   = (const float*)d_in[1];
    const int*   src  = (const int*)d_in[2];
    const int*   dst  = (const int*)d_in[3];
    const int*   bat  = (const int*)d_in[4];
    const float* eps1 = (const float*)d_in[5];
    const float* We1  = (const float*)d_in[6];
    const float* be1  = (const float*)d_in[7];
    const float* W11  = (const float*)d_in[8];
    const float* b11  = (const float*)d_in[9];
    const float* W12  = (const float*)d_in[10];
    const float* b12  = (const float*)d_in[11];
    const float* eps2 = (const float*)d_in[12];
    const float* We2  = (const float*)d_in[13];
    const float* be2  = (const float*)d_in[14];
    const float* W21  = (const float*)d_in[15];
    const float* b21  = (const float*)d_in[16];
    const float* W22  = (const float*)d_in[17];
    const float* b22  = (const float*)d_in[18];
    const float* Wf1  = (const float*)d_in[19];
    const float* bf1  = (const float*)d_in[20];
    const float* Wf2  = (const float*)d_in[21];
    const float* bf2  = (const float*)d_in[22];

    void *aggr_p, *h1_p, *pool_p;
    cudaGetSymbolAddress(&aggr_p, g_aggr);
    cudaGetSymbolAddress(&h1_p, g_h1);
    cudaGetSymbolAddress(&pool_p, g_pool);
    float4* aggr4 = (float4*)aggr_p;
    float4* h1_4  = (float4*)h1_p;
    float4* pool4 = (float4*)pool_p;
    float*  pool  = (float*)pool_p;

    static bool attr_done = false;
    if (!attr_done) {
        cudaFuncSetAttribute(k_mlp<false>, cudaFuncAttributeMaxDynamicSharedMemorySize, MLP_SMEM);
        cudaFuncSetAttribute(k_mlp<true>,  cudaFuncAttributeMaxDynamicSharedMemorySize, MLP_SMEM);
        attr_done = true;
    }

    const int INIT_BLOCKS = (N_NODES * 16) / 256;                // 6250
    const int EDGE_BLOCKS = N_EDGES / EPB;                       // 6250
    const int MLP_BLOCKS  = (N_NODES + MLP_NPB - 1) / MLP_NPB;   // 391

    cudaMemsetAsync(pool_p, 0, N_GRAPHS * 64 * sizeof(float));

    // ---- conv1 ----
    k_init<<<INIT_BLOCKS, 256>>>((const float4*)x, eps1, aggr4);
    k_edge<<<EDGE_BLOCKS, 160>>>((const float4*)x, (const float4*)ea, src, dst,
                                 (const float4*)We1, (const float4*)be1, aggr4);
    k_mlp<false><<<MLP_BLOCKS, 256, MLP_SMEM>>>((const float4*)aggr_p,
                                                (const float4*)W11, (const float4*)b11,
                                                (const float4*)W12, (const float4*)b12,
                                                h1_4, eps2, aggr4, nullptr, nullptr);
    // ---- conv2 ----
    k_edge<<<EDGE_BLOCKS, 160>>>((const float4*)h1_p, (const float4*)ea, src, dst,
                                 (const float4*)We2, (const float4*)be2, aggr4);
    k_mlp<true><<<MLP_BLOCKS, 256, MLP_SMEM>>>((const float4*)aggr_p,
                                               (const float4*)W21, (const float4*)b21,
                                               (const float4*)W22, (const float4*)b22,
                                               nullptr, nullptr, nullptr, bat, pool4);
    // ---- head ----
    k_head<<<1, 128>>>(pool, Wf1, bf1, Wf2, bf2, (float*)d_out);
}

// round 17
// speedup vs baseline: 1.1445x; 1.1445x over previous
#include <cuda_runtime.h>

#define N_NODES 100000
#define N_EDGES 1000000
#define N_GRAPHS 128

typedef unsigned long long u64t;

// ---------------- packed f32x2 helpers --------------------------------------
__device__ __forceinline__ u64t ffma2(u64t a, u64t b, u64t c) {
    u64t d;
    asm("fma.rn.f32x2 %0, %1, %2, %3;" : "=l"(d) : "l"(a), "l"(b), "l"(c));
    return d;
}
__device__ __forceinline__ u64t pack2(float lo, float hi) {
    u64t r;
    asm("mov.b64 %0, {%1, %2};" : "=l"(r) : "f"(lo), "f"(hi));
    return r;
}
__device__ __forceinline__ float2 unpack2(u64t v) {
    float2 r;
    asm("mov.b64 {%0, %1}, %2;" : "=f"(r.x), "=f"(r.y) : "l"(v));
    return r;
}

// ---------------- scratch ----------------------------------------------------
__device__ __align__(16) float g_aggr[N_NODES * 64];
__device__ __align__(16) float g_h1[N_NODES * 64];
__device__ __align__(16) float g_pool[N_GRAPHS * 64];

// ---------------- aggr = (1+eps1) * x ---------------------------------------
__global__ __launch_bounds__(256) void k_init(const float4* __restrict__ x,
                                              const float* __restrict__ eps,
                                              float4* __restrict__ aggr) {
    int i = blockIdx.x * blockDim.x + threadIdx.x;
    float s = 1.0f + *eps;
    float4 v = x[i];
    v.x *= s; v.y *= s; v.z *= s; v.w *= s;
    aggr[i] = v;
}

// ---------------- edge kernel (R10 — best measured) --------------------------
// 160 edges x 64 cols / 160-thread block; thread tile 8 edges x 8 cols.
// SPLIT-CHUNK col mapping: thread cg covers float4 idx cg (cols 4cg..4cg+3)
// and float4 idx 8+cg (cols 32+4cg..+3) -> gathers and REDs touch ONE 128B
// line per edge per instruction. Natural-order packed weights, two
// conflict-free LDS.128 per k. 3 blocks/SM (regs=128; occupancy structurally
// capped — do not force, see R6/R8/R16 post-mortems).
#define EPB 160
__global__ void __launch_bounds__(160, 3)
k_edge(const float4* __restrict__ x4,
       const float4* __restrict__ ea4,
       const int* __restrict__ src,
       const int* __restrict__ dst,
       const float4* __restrict__ We4,
       const float4* __restrict__ be4,
       float4* __restrict__ aggr4) {
    __shared__ float4 sEA4[EPB * 9];   // [e][9]; chunk q stored at q^((e>>3)&3)
    __shared__ u64t   sW[32][32];      // [k][pair] natural order
    __shared__ int    sDst[EPB];

    const int tid   = threadIdx.x;
    const int e0    = blockIdx.x * EPB;
    const int cg    = tid & 7;
    const int eg    = tid >> 3;
    const int ebase = eg * 8;
    const int fA    = cg;              // first 128B line of node row
    const int fB    = 8 + cg;          // second 128B line
    const int sw    = eg & 3;

    // early gather: src ids then x rows (latency hides behind staging + sync)
    int mySrc[8];
#pragma unroll
    for (int i = 0; i < 8; i++) mySrc[i] = __ldg(&src[e0 + ebase + i]);
    float4 xa[8], xb[8];
#pragma unroll
    for (int i = 0; i < 8; i++) {
        xa[i] = __ldg(&x4[(size_t)mySrc[i] * 16 + fA]);
        xb[i] = __ldg(&x4[(size_t)mySrc[i] * 16 + fB]);
    }

    // stage We: natural pair order (float4 c4 -> pairs 2c4, 2c4+1)
    for (int i = tid; i < 512; i += EPB) {
        int k = i >> 4, c4 = i & 15;
        float4 v = We4[i];
        sW[k][2 * c4]     = pack2(v.x, v.y);
        sW[k][2 * c4 + 1] = pack2(v.z, v.w);
    }
    // stage ea (xor-swizzled float4 chunks) + dst
#pragma unroll
    for (int i = tid; i < EPB * 8; i += EPB) {
        int e = i >> 3, q = i & 7;
        sEA4[e * 9 + (q ^ ((e >> 3) & 3))] = ea4[(size_t)(e0 + e) * 8 + q];
    }
    if (tid < EPB) sDst[tid] = dst[e0 + tid];
    __syncthreads();

    // acc init = be + x[src]
    float4 b0 = __ldg(&be4[fA]);
    float4 b1 = __ldg(&be4[fB]);
    u64t acc[8][4];
#pragma unroll
    for (int i = 0; i < 8; i++) {
        acc[i][0] = pack2(b0.x + xa[i].x, b0.y + xa[i].y);
        acc[i][1] = pack2(b0.z + xa[i].z, b0.w + xa[i].w);
        acc[i][2] = pack2(b1.x + xb[i].x, b1.y + xb[i].y);
        acc[i][3] = pack2(b1.z + xb[i].z, b1.w + xb[i].w);
    }

    // mainloop: 4-edge sub-batches
#pragma unroll
    for (int k4 = 0; k4 < 8; k4++) {
#pragma unroll
        for (int h = 0; h < 2; h++) {
            float4 eav[4];
#pragma unroll
            for (int i = 0; i < 4; i++)
                eav[i] = sEA4[(ebase + h * 4 + i) * 9 + (k4 ^ sw)];
#pragma unroll
            for (int kk = 0; kk < 4; kk++) {
                int k = k4 * 4 + kk;
                ulonglong2 wA = *(const ulonglong2*)&sW[k][2 * cg];
                ulonglong2 wB = *(const ulonglong2*)&sW[k][16 + 2 * cg];
#pragma unroll
                for (int i = 0; i < 4; i++) {
                    int e = h * 4 + i;
                    float a = (kk == 0) ? eav[i].x : (kk == 1) ? eav[i].y
                            : (kk == 2) ? eav[i].z : eav[i].w;
                    u64t aa = pack2(a, a);
                    acc[e][0] = ffma2(aa, wA.x, acc[e][0]);
                    acc[e][1] = ffma2(aa, wA.y, acc[e][1]);
                    acc[e][2] = ffma2(aa, wB.x, acc[e][2]);
                    acc[e][3] = ffma2(aa, wB.y, acc[e][3]);
                }
            }
        }
    }

    // epilogue: relu + scatter-add (1 line/edge/instr, fire-and-forget)
#pragma unroll
    for (int e = 0; e < 8; e++) {
        float2 v0 = unpack2(acc[e][0]);
        float2 v1 = unpack2(acc[e][1]);
        float2 v2 = unpack2(acc[e][2]);
        float2 v3 = unpack2(acc[e][3]);
        float4 m0, m1;
        m0.x = fmaxf(v0.x, 0.0f); m0.y = fmaxf(v0.y, 0.0f);
        m0.z = fmaxf(v1.x, 0.0f); m0.w = fmaxf(v1.y, 0.0f);
        m1.x = fmaxf(v2.x, 0.0f); m1.y = fmaxf(v2.y, 0.0f);
        m1.z = fmaxf(v3.x, 0.0f); m1.w = fmaxf(v3.y, 0.0f);
        int d = sDst[ebase + e];
        atomicAdd(&aggr4[(size_t)d * 16 + fA], m0);
        atomicAdd(&aggr4[(size_t)d * 16 + fB], m1);
    }
}

// ---------------- node MLP v2 (best measured) --------------------------------
// 256 nodes / 256-thread block; thread = 8 nodes x 8 cols. Transposed
// activations (broadcast LDS.128), f32x2 FMA, pool fused into epilogue.
#define MLP_NPB 256
#define PADF 260
#define MLP_SMEM (2 * 64 * 64 * 4 + 64 * PADF * 4)
template <bool POOL>
__global__ void __launch_bounds__(256, 2)
k_mlp(const float4* __restrict__ hin4,
      const float4* __restrict__ W1_4,
      const float4* __restrict__ b1_4,
      const float4* __restrict__ W2_4,
      const float4* __restrict__ b2_4,
      float4* __restrict__ hout4,
      const float* __restrict__ eps_next,
      float4* __restrict__ aggr_next,
      const int* __restrict__ batch,
      float4* __restrict__ pool4) {
    extern __shared__ char smem_raw[];
    float4* sW1f4 = (float4*)smem_raw;
    float4* sW2f4 = sW1f4 + 64 * 16;
    float*  sHT   = (float*)(sW2f4 + 64 * 16);

    const int tid = threadIdx.x;
    const int n0  = blockIdx.x * MLP_NPB;
    const int cg  = tid & 7;
    const int ng  = tid >> 3;

    for (int i = tid; i < 1024; i += 256) {
        sW1f4[i] = W1_4[i];
        sW2f4[i] = W2_4[i];
    }
    for (int i = tid; i < MLP_NPB * 16; i += 256) {
        int n = i & 255, k4 = i >> 8;
        float4 v = (n0 + n < N_NODES) ? hin4[(size_t)(n0 + n) * 16 + k4]
                                      : make_float4(0.f, 0.f, 0.f, 0.f);
        sHT[(4 * k4 + 0) * PADF + n] = v.x;
        sHT[(4 * k4 + 1) * PADF + n] = v.y;
        sHT[(4 * k4 + 2) * PADF + n] = v.z;
        sHT[(4 * k4 + 3) * PADF + n] = v.w;
    }
    __syncthreads();

    u64t acc[4][8];
    {
        float4 ba = __ldg(&b1_4[cg]);
        float4 bb = __ldg(&b1_4[8 + cg]);
        u64t bi[8] = { pack2(ba.x, ba.x), pack2(ba.y, ba.y),
                       pack2(ba.z, ba.z), pack2(ba.w, ba.w),
                       pack2(bb.x, bb.x), pack2(bb.y, bb.y),
                       pack2(bb.z, bb.z), pack2(bb.w, bb.w) };
#pragma unroll
        for (int np = 0; np < 4; np++)
#pragma unroll
            for (int c = 0; c < 8; c++) acc[np][c] = bi[c];
    }

#pragma unroll 8
    for (int k = 0; k < 64; k++) {
        ulonglong2 hA = *(const ulonglong2*)&sHT[k * PADF + 8 * ng];
        ulonglong2 hB = *(const ulonglong2*)&sHT[k * PADF + 8 * ng + 4];
        float4 wa = sW1f4[k * 16 + cg];
        float4 wb = sW1f4[k * 16 + 8 + cg];
        u64t w2[8] = { pack2(wa.x, wa.x), pack2(wa.y, wa.y),
                       pack2(wa.z, wa.z), pack2(wa.w, wa.w),
                       pack2(wb.x, wb.x), pack2(wb.y, wb.y),
                       pack2(wb.z, wb.z), pack2(wb.w, wb.w) };
        u64t hp[4] = { hA.x, hA.y, hB.x, hB.y };
#pragma unroll
        for (int np = 0; np < 4; np++)
#pragma unroll
            for (int c = 0; c < 8; c++)
                acc[np][c] = ffma2(hp[np], w2[c], acc[np][c]);
    }
    __syncthreads();
#pragma unroll
    for (int np = 0; np < 4; np++) {
#pragma unroll
        for (int c = 0; c < 8; c++) {
            float2 v = unpack2(acc[np][c]);
            int cglob = (c < 4) ? (4 * cg + c) : (32 + 4 * cg + (c - 4));
            float2 t = make_float2(fmaxf(v.x, 0.0f), fmaxf(v.y, 0.0f));
            *(float2*)&sHT[cglob * PADF + 8 * ng + 2 * np] = t;
        }
    }
    __syncthreads();

    {
        float4 ba = __ldg(&b2_4[cg]);
        float4 bb = __ldg(&b2_4[8 + cg]);
        u64t bi[8] = { pack2(ba.x, ba.x), pack2(ba.y, ba.y),
                       pack2(ba.z, ba.z), pack2(ba.w, ba.w),
                       pack2(bb.x, bb.x), pack2(bb.y, bb.y),
                       pack2(bb.z, bb.z), pack2(bb.w, bb.w) };
#pragma unroll
        for (int np = 0; np < 4; np++)
#pragma unroll
            for (int c = 0; c < 8; c++) acc[np][c] = bi[c];
    }
#pragma unroll 8
    for (int k = 0; k < 64; k++) {
        ulonglong2 hA = *(const ulonglong2*)&sHT[k * PADF + 8 * ng];
        ulonglong2 hB = *(const ulonglong2*)&sHT[k * PADF + 8 * ng + 4];
        float4 wa = sW2f4[k * 16 + cg];
        float4 wb = sW2f4[k * 16 + 8 + cg];
        u64t w2[8] = { pack2(wa.x, wa.x), pack2(wa.y, wa.y),
                       pack2(wa.z, wa.z), pack2(wa.w, wa.w),
                       pack2(wb.x, wb.x), pack2(wb.y, wb.y),
                       pack2(wb.z, wb.z), pack2(wb.w, wb.w) };
        u64t hp[4] = { hA.x, hA.y, hB.x, hB.y };
#pragma unroll
        for (int np = 0; np < 4; np++)
#pragma unroll
            for (int c = 0; c < 8; c++)
                acc[np][c] = ffma2(hp[np], w2[c], acc[np][c]);
    }

    float s = POOL ? 0.0f : (1.0f + __ldg(eps_next));
#pragma unroll
    for (int np = 0; np < 4; np++) {
        float2 p[8];
#pragma unroll
        for (int c = 0; c < 8; c++) p[c] = unpack2(acc[np][c]);
#pragma unroll
        for (int b = 0; b < 2; b++) {
            int node = n0 + 8 * ng + 2 * np + b;
            if (node >= N_NODES) continue;
            float4 oA, oB;
            oA.x = fmaxf(b ? p[0].y : p[0].x, 0.0f);
            oA.y = fmaxf(b ? p[1].y : p[1].x, 0.0f);
            oA.z = fmaxf(b ? p[2].y : p[2].x, 0.0f);
            oA.w = fmaxf(b ? p[3].y : p[3].x, 0.0f);
            oB.x = fmaxf(b ? p[4].y : p[4].x, 0.0f);
            oB.y = fmaxf(b ? p[5].y : p[5].x, 0.0f);
            oB.z = fmaxf(b ? p[6].y : p[6].x, 0.0f);
            oB.w = fmaxf(b ? p[7].y : p[7].x, 0.0f);
            if (POOL) {
                int g = __ldg(&batch[node]);
                atomicAdd(&pool4[(size_t)g * 16 + cg], oA);
                atomicAdd(&pool4[(size_t)g * 16 + 8 + cg], oB);
            } else {
                hout4[(size_t)node * 16 + cg]     = oA;
                hout4[(size_t)node * 16 + 8 + cg] = oB;
                float4 zA, zB;
                zA.x = s * oA.x; zA.y = s * oA.y; zA.z = s * oA.z; zA.w = s * oA.w;
                zB.x = s * oB.x; zB.y = s * oB.y; zB.z = s * oB.z; zB.w = s * oB.w;
                aggr_next[(size_t)node * 16 + cg]     = zA;
                aggr_next[(size_t)node * 16 + 8 + cg] = zB;
            }
        }
    }
}

// ---------------- head -------------------------------------------------------
__global__ __launch_bounds__(128) void k_head(const float* __restrict__ pool,
                                              const float* __restrict__ Wf1,
                                              const float* __restrict__ bf1,
                                              const float* __restrict__ Wf2,
                                              const float* __restrict__ bf2,
                                              float* __restrict__ out) {
    __shared__ float sW[64][128];
    const int tid = threadIdx.x;
    for (int i = tid; i < 64 * 128; i += 128) sW[i >> 7][i & 127] = Wf1[i];
    __syncthreads();

    float p[64];
#pragma unroll
    for (int k = 0; k < 64; k++) p[k] = pool[tid * 64 + k];

    float o = 0.0f;
    for (int j = 0; j < 128; j++) {
        float s = bf1[j];
#pragma unroll
        for (int k = 0; k < 64; k++) s = fmaf(p[k], sW[k][j], s);
        o = fmaf(fmaxf(s, 0.0f), Wf2[j], o);
    }
    out[tid] = o + bf2[0];
}

// ---------------- launch -----------------------------------------------------
extern "C" void kernel_launch(void* const* d_in, const int* in_sizes, int n_in,
                              void* d_out, int out_size) {
    const float* x    = (const float*)d_in[0];
    const float* ea   = (const float*)d_in[1];
    const int*   src  = (const int*)d_in[2];
    const int*   dst  = (const int*)d_in[3];
    const int*   bat  = (const int*)d_in[4];
    const float* eps1 = (const float*)d_in[5];
    const float* We1  = (const float*)d_in[6];
    const float* be1  = (const float*)d_in[7];
    const float* W11  = (const float*)d_in[8];
    const float* b11  = (const float*)d_in[9];
    const float* W12  = (const float*)d_in[10];
    const float* b12  = (const float*)d_in[11];
    const float* eps2 = (const float*)d_in[12];
    const float* We2  = (const float*)d_in[13];
    const float* be2  = (const float*)d_in[14];
    const float* W21  = (const float*)d_in[15];
    const float* b21  = (const float*)d_in[16];
    const float* W22  = (const float*)d_in[17];
    const float* b22  = (const float*)d_in[18];
    const float* Wf1  = (const float*)d_in[19];
    const float* bf1  = (const float*)d_in[20];
    const float* Wf2  = (const float*)d_in[21];
    const float* bf2  = (const float*)d_in[22];

    void *aggr_p, *h1_p, *pool_p;
    cudaGetSymbolAddress(&aggr_p, g_aggr);
    cudaGetSymbolAddress(&h1_p, g_h1);
    cudaGetSymbolAddress(&pool_p, g_pool);
    float4* aggr4 = (float4*)aggr_p;
    float4* h1_4  = (float4*)h1_p;
    float4* pool4 = (float4*)pool_p;
    float*  pool  = (float*)pool_p;

    static bool attr_done = false;
    if (!attr_done) {
        cudaFuncSetAttribute(k_mlp<false>, cudaFuncAttributeMaxDynamicSharedMemorySize, MLP_SMEM);
        cudaFuncSetAttribute(k_mlp<true>,  cudaFuncAttributeMaxDynamicSharedMemorySize, MLP_SMEM);
        attr_done = true;
    }

    const int INIT_BLOCKS = (N_NODES * 16) / 256;                // 6250
    const int EDGE_BLOCKS = N_EDGES / EPB;                       // 6250
    const int MLP_BLOCKS  = (N_NODES + MLP_NPB - 1) / MLP_NPB;   // 391

    cudaMemsetAsync(pool_p, 0, N_GRAPHS * 64 * sizeof(float));

    // ---- conv1 ----
    k_init<<<INIT_BLOCKS, 256>>>((const float4*)x, eps1, aggr4);
    k_edge<<<EDGE_BLOCKS, 160>>>((const float4*)x, (const float4*)ea, src, dst,
                                 (const float4*)We1, (const float4*)be1, aggr4);
    k_mlp<false><<<MLP_BLOCKS, 256, MLP_SMEM>>>((const float4*)aggr_p,
                                                (const float4*)W11, (const float4*)b11,
                                                (const float4*)W12, (const float4*)b12,
                                                h1_4, eps2, aggr4, nullptr, nullptr);
    // ---- conv2 ----
    k_edge<<<EDGE_BLOCKS, 160>>>((const float4*)h1_p, (const float4*)ea, src, dst,
                                 (const float4*)We2, (const float4*)be2, aggr4);
    k_mlp<true><<<MLP_BLOCKS, 256, MLP_SMEM>>>((const float4*)aggr_p,
                                               (const float4*)W21, (const float4*)b21,
                                               (const float4*)W22, (const float4*)b22,
                                               nullptr, nullptr, nullptr, bat, pool4);
    // ---- head ----
    k_head<<<1, 128>>>(pool, Wf1, bf1, Wf2, bf2, (float*)d_out);
}